// round 15
// baseline (speedup 1.0000x reference)
#include <cuda_runtime.h>
#include <cuda_fp16.h>
#include <math.h>
#include <stdint.h>

#define DIM 1536
#define NH 12
#define HD 128
#define CPAIR 64
#define MAXL 2400
#define EPS 1e-6f
#define ATT_SCALE 0.08838834764831843f   // 1/sqrt(128)
#define SCALE_L2E (ATT_SCALE * 1.4426950408889634f)

// ---------------- scratch (device globals; no allocation allowed) ----------
__device__ __half g_xh[MAXL * DIM];
__device__ __half g_wh[4 * DIM * DIM];
__device__ __half g_qh[MAXL * DIM];
__device__ __half g_kh[MAXL * DIM];
__device__ __half g_vh[MAXL * DIM];
__device__ __half g_ah[MAXL * DIM];

// ===========================================================================
// helpers
// ===========================================================================
__device__ __forceinline__ unsigned smem_u32(const void* p) {
    unsigned a;
    asm("{.reg .u64 t; cvta.to.shared.u64 t, %1; cvt.u32.u64 %0, t;}"
        : "=r"(a) : "l"(p));
    return a;
}

#define LDSM4(r0, r1, r2, r3, addr) \
    asm volatile("ldmatrix.sync.aligned.m8n8.x4.shared.b16 {%0,%1,%2,%3}, [%4];" \
                 : "=r"(r0), "=r"(r1), "=r"(r2), "=r"(r3) : "r"(addr))

#define LDSM4T(r0, r1, r2, r3, addr) \
    asm volatile("ldmatrix.sync.aligned.m8n8.x4.trans.shared.b16 {%0,%1,%2,%3}, [%4];" \
                 : "=r"(r0), "=r"(r1), "=r"(r2), "=r"(r3) : "r"(addr))

__device__ __forceinline__ void mma16(float* c, const uint32_t* a,
                                      uint32_t b0, uint32_t b1) {
    asm volatile(
        "mma.sync.aligned.m16n8k16.row.col.f32.f16.f16.f32 "
        "{%0,%1,%2,%3}, {%4,%5,%6,%7}, {%8,%9}, {%0,%1,%2,%3};\n"
        : "+f"(c[0]), "+f"(c[1]), "+f"(c[2]), "+f"(c[3])
        : "r"(a[0]), "r"(a[1]), "r"(a[2]), "r"(a[3]), "r"(b0), "r"(b1));
}

__device__ __forceinline__ uint32_t packh2(float lo, float hi) {
    __half2 h = __floats2half2_rn(lo, hi);
    return *(uint32_t*)&h;
}

__device__ __forceinline__ uint32_t hex2(uint32_t x) {
    uint32_t y;
    asm("ex2.approx.f16x2 %0, %1;" : "=r"(y) : "r"(x));
    return y;
}

// ===========================================================================
// convert x + 4 weight matrices fp32 -> fp16 in one launch
// ===========================================================================
__global__ void cvt_all_kernel(const float* __restrict__ x,
                               const float* __restrict__ Wq,
                               const float* __restrict__ Wk,
                               const float* __restrict__ Wv,
                               const float* __restrict__ Wo,
                               __half* __restrict__ xh,
                               __half* __restrict__ wh,
                               int nX4, int nW4) {
    int i = blockIdx.x * blockDim.x + threadIdx.x;
    const float4* src;
    uint2* dst;
    int j;
    if (i < nX4) {
        src = (const float4*)x; dst = (uint2*)xh; j = i;
    } else {
        int t = i - nX4;
        int w = t / nW4;
        if (w >= 4) return;
        j = t - w * nW4;
        src = (const float4*)((w == 0) ? Wq : (w == 1) ? Wk : (w == 2) ? Wv : Wo);
        dst = (uint2*)(wh + (size_t)w * nW4 * 4);
    }
    float4 v = src[j];
    dst[j] = make_uint2(packh2(v.x, v.y), packh2(v.z, v.w));
}

// ===========================================================================
// fp16 mma GEMM: 128x128 tile, BK=64, 256 thr, 2 CTAs/SM, 3-stage cp.async.
// ===========================================================================
#define HSTRB 144
#define HTILE_B (128 * HSTRB)
#define HBUF_B (2 * HTILE_B)          // one stage (A+B) = 36864
#define GNSTG 3
#define HGEMM_SMEM (GNSTG * HBUF_B)   // 110592

__device__ __forceinline__ void cp_tile_h(char* sbuf,
                                          const __half* __restrict__ A,
                                          const __half* __restrict__ B,
                                          int bm, int bn, int M, int K,
                                          int kt, int tid) {
#pragma unroll
    for (int i = 0; i < 8; i++) {
        int s = tid + i * 256;
        int mat = s >> 10;
        int idx = s & 1023;
        int row = idx >> 3, quad = idx & 7;
        unsigned dst = smem_u32(sbuf + mat * HTILE_B + row * HSTRB + quad * 16);
        const __half* src;
        int sz = 16;
        if (mat == 0) {
            int gr = bm + row;
            src = A + (size_t)((gr < M) ? gr : 0) * K + kt + quad * 8;
            sz = (gr < M) ? 16 : 0;
        } else {
            src = B + (size_t)(bn + row) * K + kt + quad * 8;
        }
        asm volatile("cp.async.cg.shared.global [%0], [%1], 16, %2;\n"
                     :: "r"(dst), "l"(src), "r"(sz));
    }
    asm volatile("cp.async.commit_group;\n");
}

__device__ __forceinline__ void compute_tile_h(const char* sbuf,
                                               float acc[4][4][4],
                                               unsigned laneA, unsigned laneB) {
    const unsigned aB = smem_u32(sbuf) + laneA;
    const unsigned bB = smem_u32(sbuf) + HTILE_B + laneB;
#pragma unroll
    for (int kk = 0; kk < 4; kk++) {
        uint32_t af[4][4], bf[2][4];
#pragma unroll
        for (int ma = 0; ma < 4; ma++)
            LDSM4(af[ma][0], af[ma][1], af[ma][2], af[ma][3],
                  aB + ma * (16 * HSTRB) + kk * 32);
#pragma unroll
        for (int p = 0; p < 2; p++)
            LDSM4(bf[p][0], bf[p][1], bf[p][2], bf[p][3],
                  bB + p * (16 * HSTRB) + kk * 32);
#pragma unroll
        for (int ma = 0; ma < 4; ma++)
#pragma unroll
            for (int na = 0; na < 4; na++)
                mma16(acc[ma][na], af[ma],
                      bf[na >> 1][(na & 1) * 2], bf[na >> 1][(na & 1) * 2 + 1]);
    }
}

__global__ __launch_bounds__(256, 2)
void gemm_h_kernel(const __half* __restrict__ A, const __half* __restrict__ W,
                   const float* __restrict__ b0v, const float* __restrict__ b1v,
                   const float* __restrict__ b2v,
                   void* __restrict__ C0, void* __restrict__ C1,
                   void* __restrict__ C2,
                   int M, int nmat, int outHalf) {
    extern __shared__ char smh[];
    const int tid = threadIdx.x;
    const int lane = tid & 31;
    const int wid = tid >> 5;
    const int gid = lane >> 2, tig = lane & 3;
    const int warp_m = wid >> 2, warp_n = wid & 3;
    const int bm = blockIdx.y * 128, bn = blockIdx.x * 128;
    const int K = DIM;

    const int z = (nmat == 3) ? blockIdx.z : 0;
    const __half* B = W + (size_t)z * DIM * DIM;
    const float* bias = (z == 0) ? b0v : (z == 1) ? b1v : b2v;
    void* C = (z == 0) ? C0 : (z == 1) ? C1 : C2;

    const unsigned laneA =
        (unsigned)((warp_m * 64 + (lane & 15)) * HSTRB + ((lane >> 4) & 1) * 16);
    const unsigned laneB =
        (unsigned)((warp_n * 32 + (lane & 7) + ((lane >> 4) & 1) * 8) * HSTRB
                   + ((lane >> 3) & 1) * 16);

    float acc[4][4][4];
#pragma unroll
    for (int i = 0; i < 4; i++)
#pragma unroll
        for (int j = 0; j < 4; j++)
#pragma unroll
            for (int r = 0; r < 4; r++) acc[i][j][r] = 0.f;

    const int nt = K / 64;   // 24

    // preload stages 0 and 1
    cp_tile_h(smh, A, B, bm, bn, M, K, 0, tid);
    cp_tile_h(smh + HBUF_B, A, B, bm, bn, M, K, 64, tid);

    // 3-stage loop: wait stage t (leave t+1 in flight) -> barrier ->
    // issue t+2 -> compute t. Buffer (t+2)%3 == (t-1)%3, whose readers
    // finished at compute(t-1), ordered by this barrier.
    int stage = 0;
    for (int t = 0; t < nt; t++) {
        if (t + 1 < nt)
            asm volatile("cp.async.wait_group 1;\n");
        else
            asm volatile("cp.async.wait_group 0;\n");
        __syncthreads();
        if (t + 2 < nt) {
            int nstage = (stage + 2 >= GNSTG) ? stage + 2 - GNSTG : stage + 2;
            cp_tile_h(smh + nstage * HBUF_B, A, B, bm, bn, M, K,
                      (t + 2) * 64, tid);
        }
        compute_tile_h(smh + stage * HBUF_B, acc, laneA, laneB);
        stage = (stage + 1 >= GNSTG) ? 0 : stage + 1;
    }

#pragma unroll
    for (int ma = 0; ma < 4; ma++) {
        int r = bm + warp_m * 64 + ma * 16 + gid;
#pragma unroll
        for (int na = 0; na < 4; na++) {
            int c = bn + warp_n * 32 + na * 8 + tig * 2;
            float2 bb = *(const float2*)&bias[c];
            float o00 = acc[ma][na][0] + bb.x, o01 = acc[ma][na][1] + bb.y;
            float o10 = acc[ma][na][2] + bb.x, o11 = acc[ma][na][3] + bb.y;
            if (outHalf) {
                __half* Ch = (__half*)C;
                if (r < M)
                    *(uint32_t*)&Ch[(size_t)r * DIM + c] = packh2(o00, o01);
                if (r + 8 < M)
                    *(uint32_t*)&Ch[(size_t)(r + 8) * DIM + c] = packh2(o10, o11);
            } else {
                float* Cf = (float*)C;
                if (r < M)
                    *(float2*)&Cf[(size_t)r * DIM + c] = make_float2(o00, o01);
                if (r + 8 < M)
                    *(float2*)&Cf[(size_t)(r + 8) * DIM + c] = make_float2(o10, o11);
            }
        }
    }
}

// ---------------------------------------------------------------------------
// Fused RMSNorm + 3D RoPE, block-per-token.
// ---------------------------------------------------------------------------
__global__ void norm_rope_h_kernel(__half* __restrict__ q, __half* __restrict__ k,
                                   const float* __restrict__ gq,
                                   const float* __restrict__ gk,
                                   const float* __restrict__ freqs,
                                   const int* __restrict__ grid_sizes) {
    const int l = blockIdx.x;
    const int tid = threadIdx.x;
    __shared__ float red[64];
    __shared__ float s_invq, s_invk;

    __half* qr = q + (size_t)l * DIM;
    __half* kr = k + (size_t)l * DIM;

    float sq = 0.f, sk = 0.f;
    for (int d = tid; d < DIM; d += blockDim.x) {
        float a = __half2float(qr[d]); sq += a * a;
        float b = __half2float(kr[d]); sk += b * b;
    }
#pragma unroll
    for (int o = 16; o; o >>= 1) {
        sq += __shfl_xor_sync(0xffffffffu, sq, o);
        sk += __shfl_xor_sync(0xffffffffu, sk, o);
    }
    int wid = tid >> 5, lid = tid & 31;
    if (lid == 0) { red[wid] = sq; red[32 + wid] = sk; }
    __syncthreads();
    if (tid == 0) {
        float t = 0.f;
        for (int i = 0; i < (int)(blockDim.x >> 5); i++) t += red[i];
        s_invq = rsqrtf(t / DIM + EPS);
    }
    if (tid == 1) {
        float t = 0.f;
        for (int i = 0; i < (int)(blockDim.x >> 5); i++) t += red[32 + i];
        s_invk = rsqrtf(t / DIM + EPS);
    }
    __syncthreads();
    const float invq = s_invq, invk = s_invk;

    const int hh = grid_sizes[1], ww = grid_sizes[2];
    const int hw = hh * ww;
    const int fi = l / hw;
    const int rem = l - fi * hw;
    const int hi = rem / ww;
    const int wi = rem - hi * ww;

    for (int p = tid; p < NH * CPAIR; p += blockDim.x) {
        int c = p & (CPAIR - 1);
        int d0 = (p >> 6) * HD + 2 * c;
        int pos = (c < 22) ? fi : ((c < 43) ? hi : wi);
        const float* R = freqs + ((size_t)pos * CPAIR + c) * 4;
        float r00 = R[0], r01 = R[1], r10 = R[2], r11 = R[3];

        float x0 = __half2float(qr[d0]) * invq * gq[d0];
        float x1 = __half2float(qr[d0 + 1]) * invq * gq[d0 + 1];
        *(uint32_t*)&qr[d0] = packh2(r00 * x0 + r01 * x1, r10 * x0 + r11 * x1);

        x0 = __half2float(kr[d0]) * invk * gk[d0];
        x1 = __half2float(kr[d0 + 1]) * invk * gk[d0 + 1];
        *(uint32_t*)&kr[d0] = packh2(r00 * x0 + r01 * x1, r10 * x0 + r11 * x1);
    }
}

// ===========================================================================
// fp16 mma flash attention, frozen-max + f16x2 exp (R13, unchanged).
// ===========================================================================
#define AQT 64
#define AKC 64
#define AKSTRB 272
#define ABUF (2 * AKC * AKSTRB)
#define ATT_SMEM (2 * ABUF)              // 69632

__device__ __forceinline__ void attn_load(char* buf,
                                          const __half* __restrict__ K,
                                          const __half* __restrict__ V,
                                          int kc, int seqlen, int head,
                                          int tid, bool full) {
#pragma unroll
    for (int it = 0; it < 16; it++) {
        int s = tid + it * 128;
        int mat = s >> 10;
        int idx = s & 1023;
        int row = idx >> 4, quad = idx & 15;
        int gk = kc + row;
        int gkc = full ? gk : ((gk < seqlen) ? gk : 0);
        const __half* src = (mat ? V : K)
            + (size_t)gkc * DIM + head * HD + quad * 8;
        unsigned dst = smem_u32(buf) + mat * (AKC * AKSTRB)
            + row * AKSTRB + quad * 16;
        int sz = (full || gk < seqlen) ? 16 : 0;
        asm volatile("cp.async.cg.shared.global [%0], [%1], 16, %2;\n"
                     :: "r"(dst), "l"(src), "r"(sz));
    }
    asm volatile("cp.async.commit_group;\n");
}

template <int MODE>   // 0 = first (sets max), 1 = full frozen, 2 = masked frozen
__device__ __forceinline__ void attn_chunk(const char* buf, int kc, int seqlen,
                                           const uint32_t qa[8][4],
                                           float oacc[16][4],
                                           float& m0, float& m1,
                                           float& l0, float& l1,
                                           unsigned ksOff, unsigned vsOff) {
    const unsigned ksB = smem_u32(buf) + ksOff;
    const unsigned vsB = smem_u32(buf) + AKC * AKSTRB + vsOff;
    const int lane = threadIdx.x & 31;
    const int tig = lane & 3;

    // ---- S = Q @ K^T ----
    float sacc[8][4];
#pragma unroll
    for (int na = 0; na < 8; na++)
#pragma unroll
        for (int j = 0; j < 4; j++) sacc[na][j] = 0.f;
#pragma unroll
    for (int kk = 0; kk < 8; kk++) {
#pragma unroll
        for (int p = 0; p < 4; p++) {
            uint32_t b[4];
            LDSM4(b[0], b[1], b[2], b[3], ksB + p * (16 * AKSTRB) + kk * 32);
            mma16(sacc[2 * p], qa[kk], b[0], b[1]);
            mma16(sacc[2 * p + 1], qa[kk], b[2], b[3]);
        }
    }

    if (MODE == 0) {
        float mx0 = -1e30f, mx1 = -1e30f;
#pragma unroll
        for (int na = 0; na < 8; na++) {
            mx0 = fmaxf(mx0, fmaxf(sacc[na][0], sacc[na][1]));
            mx1 = fmaxf(mx1, fmaxf(sacc[na][2], sacc[na][3]));
        }
#pragma unroll
        for (int o = 1; o <= 2; o <<= 1) {
            mx0 = fmaxf(mx0, __shfl_xor_sync(0xffffffffu, mx0, o));
            mx1 = fmaxf(mx1, __shfl_xor_sync(0xffffffffu, mx1, o));
        }
        m0 = mx0 * SCALE_L2E; m1 = mx1 * SCALE_L2E;
    }

    // ---- fused exp (f16x2) + PV ----
    __half2 lacc01 = __floats2half2_rn(0.f, 0.f);
    __half2 lacc23 = __floats2half2_rn(0.f, 0.f);
#pragma unroll
    for (int j = 0; j < 4; j++) {
        uint32_t pa[4];
#pragma unroll
        for (int h = 0; h < 2; h++) {
            int na = 2 * j + h;
            float u0 = fmaf(sacc[na][0], SCALE_L2E, -m0);
            float u1 = fmaf(sacc[na][1], SCALE_L2E, -m0);
            float u2 = fmaf(sacc[na][2], SCALE_L2E, -m1);
            float u3 = fmaf(sacc[na][3], SCALE_L2E, -m1);
            if (MODE == 2) {
                int col = kc + na * 8 + 2 * tig;
                if (col >= seqlen)     { u0 = -100.f; u2 = -100.f; }
                if (col + 1 >= seqlen) { u1 = -100.f; u3 = -100.f; }
            }
            uint32_t p01 = hex2(packh2(u0, u1));
            uint32_t p23 = hex2(packh2(u2, u3));
            lacc01 = __hadd2(lacc01, *(__half2*)&p01);
            lacc23 = __hadd2(lacc23, *(__half2*)&p23);
            pa[2 * h] = p01; pa[2 * h + 1] = p23;
        }
#pragma unroll
        for (int dp = 0; dp < 8; dp++) {
            uint32_t b[4];
            LDSM4T(b[0], b[1], b[2], b[3], vsB + j * (16 * AKSTRB) + dp * 32);
            mma16(oacc[2 * dp], pa, b[0], b[1]);
            mma16(oacc[2 * dp + 1], pa, b[2], b[3]);
        }
    }
    float2 f01 = __half22float2(lacc01);
    float2 f23 = __half22float2(lacc23);
    l0 += f01.x + f01.y;
    l1 += f23.x + f23.y;
}

__global__ __launch_bounds__(128, 3)
void attn_h_kernel(const __half* __restrict__ Q, const __half* __restrict__ K,
                   const __half* __restrict__ V, __half* __restrict__ O,
                   const int* __restrict__ seq_lens, int Ltot) {
    extern __shared__ char smh[];

    const int head = blockIdx.y;
    const int q0 = blockIdx.x * AQT;
    const int tid = threadIdx.x;
    const int w = tid >> 5;
    const int lane = tid & 31;
    const int gid = lane >> 2, tig = lane & 3;
    const int seqlen = seq_lens[0];

    const unsigned ksOff =
        (unsigned)(((lane & 7) + ((lane >> 4) & 1) * 8) * AKSTRB
                   + ((lane >> 3) & 1) * 16);
    const unsigned vsOff =
        (unsigned)(((lane & 7) + ((lane >> 3) & 1) * 8) * AKSTRB
                   + ((lane >> 4) & 1) * 16);

    const int r0 = q0 + w * 16 + gid;
    const int r1 = r0 + 8;
    const __half* q0p = Q + (size_t)((r0 < Ltot) ? r0 : (Ltot - 1)) * DIM + head * HD;
    const __half* q1p = Q + (size_t)((r1 < Ltot) ? r1 : (Ltot - 1)) * DIM + head * HD;

    uint32_t qa[8][4];
#pragma unroll
    for (int kk = 0; kk < 8; kk++) {
        qa[kk][0] = *(const uint32_t*)&q0p[kk * 16 + 2 * tig];
        qa[kk][1] = *(const uint32_t*)&q1p[kk * 16 + 2 * tig];
        qa[kk][2] = *(const uint32_t*)&q0p[kk * 16 + 8 + 2 * tig];
        qa[kk][3] = *(const uint32_t*)&q1p[kk * 16 + 8 + 2 * tig];
    }

    float oacc[16][4];
#pragma unroll
    for (int i = 0; i < 16; i++)
#pragma unroll
        for (int j = 0; j < 4; j++) oacc[i][j] = 0.f;
    float m0 = 0.f, m1 = 0.f, l0 = 0.f, l1 = 0.f;

    const int nchunk = (seqlen + AKC - 1) / AKC;
    const int nfull = seqlen / AKC;

    attn_load(smh, K, V, 0, seqlen, head, tid, 0 < nfull);

    for (int ch = 0; ch < nchunk; ch++) {
        asm volatile("cp.async.wait_group 0;\n");
        __syncthreads();
        if (ch + 1 < nchunk)
            attn_load(smh + ((ch + 1) & 1) * ABUF, K, V, (ch + 1) * AKC,
                      seqlen, head, tid, (ch + 1) < nfull);
        const char* buf = smh + (ch & 1) * ABUF;
        if (ch == 0)
            attn_chunk<0>(buf, 0, seqlen, qa, oacc, m0, m1, l0, l1, ksOff, vsOff);
        else if (ch < nfull)
            attn_chunk<1>(buf, ch * AKC, seqlen, qa, oacc, m0, m1, l0, l1,
                          ksOff, vsOff);
        else
            attn_chunk<2>(buf, ch * AKC, seqlen, qa, oacc, m0, m1, l0, l1,
                          ksOff, vsOff);
    }

#pragma unroll
    for (int o = 1; o <= 2; o <<= 1) {
        l0 += __shfl_xor_sync(0xffffffffu, l0, o);
        l1 += __shfl_xor_sync(0xffffffffu, l1, o);
    }

    float inv0 = (l0 > 0.f) ? 1.0f / l0 : 0.f;
    float inv1 = (l1 > 0.f) ? 1.0f / l1 : 0.f;
#pragma unroll
    for (int na = 0; na < 16; na++) {
        int c = head * HD + na * 8 + 2 * tig;
        if (r0 < Ltot)
            *(uint32_t*)&O[(size_t)r0 * DIM + c] =
                packh2(oacc[na][0] * inv0, oacc[na][1] * inv0);
        if (r1 < Ltot)
            *(uint32_t*)&O[(size_t)r1 * DIM + c] =
                packh2(oacc[na][2] * inv1, oacc[na][3] * inv1);
    }
}

// ---------------------------------------------------------------------------
// Inputs: 0:x 1:Wq 2:bq 3:Wk 4:bk 5:Wv 6:bv 7:Wo 8:bo 9:gq 10:gk
//         11:seq_lens 12:grid_sizes 13:freqs
// ---------------------------------------------------------------------------
extern "C" void kernel_launch(void* const* d_in, const int* in_sizes, int n_in,
                              void* d_out, int out_size) {
    const float* x  = (const float*)d_in[0];
    const float* Wq = (const float*)d_in[1];
    const float* bq = (const float*)d_in[2];
    const float* Wk = (const float*)d_in[3];
    const float* bk = (const float*)d_in[4];
    const float* Wv = (const float*)d_in[5];
    const float* bv = (const float*)d_in[6];
    const float* Wo = (const float*)d_in[7];
    const float* bo = (const float*)d_in[8];
    const float* gq = (const float*)d_in[9];
    const float* gk = (const float*)d_in[10];
    const int* seq_lens   = (const int*)d_in[11];
    const int* grid_sizes = (const int*)d_in[12];
    const float* freqs    = (const float*)d_in[13];
    float* out = (float*)d_out;

    const int L = in_sizes[0] / DIM;   // 2400

    __half *pxh, *pwh, *pqh, *pkh, *pvh, *pah;
    cudaGetSymbolAddress((void**)&pxh, g_xh);
    cudaGetSymbolAddress((void**)&pwh, g_wh);
    cudaGetSymbolAddress((void**)&pqh, g_qh);
    cudaGetSymbolAddress((void**)&pkh, g_kh);
    cudaGetSymbolAddress((void**)&pvh, g_vh);
    cudaGetSymbolAddress((void**)&pah, g_ah);

    cudaFuncSetAttribute(gemm_h_kernel,
                         cudaFuncAttributeMaxDynamicSharedMemorySize, HGEMM_SMEM);
    cudaFuncSetAttribute(attn_h_kernel,
                         cudaFuncAttributeMaxDynamicSharedMemorySize, ATT_SMEM);

    // --- convert inputs to fp16 ---
    const int nW4 = DIM * DIM / 4;
    const int nX4 = L * DIM / 4;
    const int tot = nX4 + 4 * nW4;
    cvt_all_kernel<<<(tot + 255) / 256, 256>>>(x, Wq, Wk, Wv, Wo,
                                               pxh, pwh, nX4, nW4);

    const int mt = (L + 127) / 128;   // 19

    // --- fused QKV projection (fp16 out) ---
    dim3 gq3(DIM / 128, mt, 3);
    gemm_h_kernel<<<gq3, 256, HGEMM_SMEM>>>(pxh, pwh, bq, bk, bv,
                                            pqh, pkh, pvh, L, 3, 1);

    norm_rope_h_kernel<<<L, 256>>>(pqh, pkh, gq, gk, freqs, grid_sizes);

    dim3 ga((L + AQT - 1) / AQT, NH);
    attn_h_kernel<<<ga, 128, ATT_SMEM>>>(pqh, pkh, pvh, pah, seq_lens, L);

    // --- output projection (fp32 out) ---
    dim3 gg(DIM / 128, mt, 1);
    gemm_h_kernel<<<gg, 256, HGEMM_SMEM>>>(pah, pwh + 3 * (size_t)DIM * DIM,
                                           bo, bo, bo, out, out, out, L, 1, 0);
}

// round 16
// speedup vs baseline: 1.0141x; 1.0141x over previous
#include <cuda_runtime.h>
#include <cuda_fp16.h>
#include <math.h>
#include <stdint.h>

#define DIM 1536
#define NH 12
#define HD 128
#define CPAIR 64
#define MAXL 2400
#define EPS 1e-6f
#define ATT_SCALE 0.08838834764831843f   // 1/sqrt(128)
#define SCALE_L2E (ATT_SCALE * 1.4426950408889634f)

// ---------------- scratch (device globals; no allocation allowed) ----------
__device__ __half g_xh[MAXL * DIM];
__device__ __half g_wh[4 * DIM * DIM];
__device__ __half g_qh[MAXL * DIM];
__device__ __half g_kh[MAXL * DIM];
__device__ __half g_vh[MAXL * DIM];
__device__ __half g_ah[MAXL * DIM];

// ===========================================================================
// helpers
// ===========================================================================
__device__ __forceinline__ unsigned smem_u32(const void* p) {
    unsigned a;
    asm("{.reg .u64 t; cvta.to.shared.u64 t, %1; cvt.u32.u64 %0, t;}"
        : "=r"(a) : "l"(p));
    return a;
}

#define LDSM4(r0, r1, r2, r3, addr) \
    asm volatile("ldmatrix.sync.aligned.m8n8.x4.shared.b16 {%0,%1,%2,%3}, [%4];" \
                 : "=r"(r0), "=r"(r1), "=r"(r2), "=r"(r3) : "r"(addr))

#define LDSM4T(r0, r1, r2, r3, addr) \
    asm volatile("ldmatrix.sync.aligned.m8n8.x4.trans.shared.b16 {%0,%1,%2,%3}, [%4];" \
                 : "=r"(r0), "=r"(r1), "=r"(r2), "=r"(r3) : "r"(addr))

__device__ __forceinline__ void mma16(float* c, const uint32_t* a,
                                      uint32_t b0, uint32_t b1) {
    asm volatile(
        "mma.sync.aligned.m16n8k16.row.col.f32.f16.f16.f32 "
        "{%0,%1,%2,%3}, {%4,%5,%6,%7}, {%8,%9}, {%0,%1,%2,%3};\n"
        : "+f"(c[0]), "+f"(c[1]), "+f"(c[2]), "+f"(c[3])
        : "r"(a[0]), "r"(a[1]), "r"(a[2]), "r"(a[3]), "r"(b0), "r"(b1));
}

__device__ __forceinline__ uint32_t packh2(float lo, float hi) {
    __half2 h = __floats2half2_rn(lo, hi);
    return *(uint32_t*)&h;
}

__device__ __forceinline__ uint32_t hex2(uint32_t x) {
    uint32_t y;
    asm("ex2.approx.f16x2 %0, %1;" : "=r"(y) : "r"(x));
    return y;
}

__device__ __forceinline__ float sumsq8(uint4 v) {
    float s = 0.f;
    float2 f;
    f = __half22float2(*(__half2*)&v.x); s += f.x * f.x + f.y * f.y;
    f = __half22float2(*(__half2*)&v.y); s += f.x * f.x + f.y * f.y;
    f = __half22float2(*(__half2*)&v.z); s += f.x * f.x + f.y * f.y;
    f = __half22float2(*(__half2*)&v.w); s += f.x * f.x + f.y * f.y;
    return s;
}

// ===========================================================================
// convert x + 4 weight matrices fp32 -> fp16 in one launch
// ===========================================================================
__global__ void cvt_all_kernel(const float* __restrict__ x,
                               const float* __restrict__ Wq,
                               const float* __restrict__ Wk,
                               const float* __restrict__ Wv,
                               const float* __restrict__ Wo,
                               __half* __restrict__ xh,
                               __half* __restrict__ wh,
                               int nX4, int nW4) {
    int i = blockIdx.x * blockDim.x + threadIdx.x;
    const float4* src;
    uint2* dst;
    int j;
    if (i < nX4) {
        src = (const float4*)x; dst = (uint2*)xh; j = i;
    } else {
        int t = i - nX4;
        int w = t / nW4;
        if (w >= 4) return;
        j = t - w * nW4;
        src = (const float4*)((w == 0) ? Wq : (w == 1) ? Wk : (w == 2) ? Wv : Wo);
        dst = (uint2*)(wh + (size_t)w * nW4 * 4);
    }
    float4 v = src[j];
    dst[j] = make_uint2(packh2(v.x, v.y), packh2(v.z, v.w));
}

// ===========================================================================
// fp16 mma GEMM (R14 best): 128x128 tile, BK=64, 256 thr, 2 CTAs/SM,
// single-barrier double-buffered cp.async loop.
// ===========================================================================
#define HSTRB 144
#define HTILE_B (128 * HSTRB)
#define HBUF_B (2 * HTILE_B)          // one stage (A+B) = 36864
#define HGEMM_SMEM (2 * HBUF_B)       // 73728

__device__ __forceinline__ void cp_tile_h(char* sbuf,
                                          const __half* __restrict__ A,
                                          const __half* __restrict__ B,
                                          int bm, int bn, int M, int K,
                                          int kt, int tid) {
#pragma unroll
    for (int i = 0; i < 8; i++) {
        int s = tid + i * 256;
        int mat = s >> 10;
        int idx = s & 1023;
        int row = idx >> 3, quad = idx & 7;
        unsigned dst = smem_u32(sbuf + mat * HTILE_B + row * HSTRB + quad * 16);
        const __half* src;
        int sz = 16;
        if (mat == 0) {
            int gr = bm + row;
            src = A + (size_t)((gr < M) ? gr : 0) * K + kt + quad * 8;
            sz = (gr < M) ? 16 : 0;
        } else {
            src = B + (size_t)(bn + row) * K + kt + quad * 8;
        }
        asm volatile("cp.async.cg.shared.global [%0], [%1], 16, %2;\n"
                     :: "r"(dst), "l"(src), "r"(sz));
    }
    asm volatile("cp.async.commit_group;\n");
}

__device__ __forceinline__ void compute_tile_h(const char* sbuf,
                                               float acc[4][4][4],
                                               unsigned laneA, unsigned laneB) {
    const unsigned aB = smem_u32(sbuf) + laneA;
    const unsigned bB = smem_u32(sbuf) + HTILE_B + laneB;
#pragma unroll
    for (int kk = 0; kk < 4; kk++) {
        uint32_t af[4][4], bf[2][4];
#pragma unroll
        for (int ma = 0; ma < 4; ma++)
            LDSM4(af[ma][0], af[ma][1], af[ma][2], af[ma][3],
                  aB + ma * (16 * HSTRB) + kk * 32);
#pragma unroll
        for (int p = 0; p < 2; p++)
            LDSM4(bf[p][0], bf[p][1], bf[p][2], bf[p][3],
                  bB + p * (16 * HSTRB) + kk * 32);
#pragma unroll
        for (int ma = 0; ma < 4; ma++)
#pragma unroll
            for (int na = 0; na < 4; na++)
                mma16(acc[ma][na], af[ma],
                      bf[na >> 1][(na & 1) * 2], bf[na >> 1][(na & 1) * 2 + 1]);
    }
}

__global__ __launch_bounds__(256, 2)
void gemm_h_kernel(const __half* __restrict__ A, const __half* __restrict__ W,
                   const float* __restrict__ b0v, const float* __restrict__ b1v,
                   const float* __restrict__ b2v,
                   void* __restrict__ C0, void* __restrict__ C1,
                   void* __restrict__ C2,
                   int M, int nmat, int outHalf) {
    extern __shared__ char smh[];
    const int tid = threadIdx.x;
    const int lane = tid & 31;
    const int wid = tid >> 5;
    const int gid = lane >> 2, tig = lane & 3;
    const int warp_m = wid >> 2, warp_n = wid & 3;
    const int bm = blockIdx.y * 128, bn = blockIdx.x * 128;
    const int K = DIM;

    const int z = (nmat == 3) ? blockIdx.z : 0;
    const __half* B = W + (size_t)z * DIM * DIM;
    const float* bias = (z == 0) ? b0v : (z == 1) ? b1v : b2v;
    void* C = (z == 0) ? C0 : (z == 1) ? C1 : C2;

    const unsigned laneA =
        (unsigned)((warp_m * 64 + (lane & 15)) * HSTRB + ((lane >> 4) & 1) * 16);
    const unsigned laneB =
        (unsigned)((warp_n * 32 + (lane & 7) + ((lane >> 4) & 1) * 8) * HSTRB
                   + ((lane >> 3) & 1) * 16);

    float acc[4][4][4];
#pragma unroll
    for (int i = 0; i < 4; i++)
#pragma unroll
        for (int j = 0; j < 4; j++)
#pragma unroll
            for (int r = 0; r < 4; r++) acc[i][j][r] = 0.f;

    const int nt = K / 64;   // 24

    cp_tile_h(smh, A, B, bm, bn, M, K, 0, tid);

    // single-barrier double-buffered loop (R14 best)
    for (int t = 0; t < nt; t++) {
        asm volatile("cp.async.wait_group 0;\n");
        __syncthreads();
        if (t + 1 < nt)
            cp_tile_h(smh + ((t + 1) & 1) * HBUF_B, A, B, bm, bn, M, K,
                      (t + 1) * 64, tid);
        compute_tile_h(smh + (t & 1) * HBUF_B, acc, laneA, laneB);
    }

#pragma unroll
    for (int ma = 0; ma < 4; ma++) {
        int r = bm + warp_m * 64 + ma * 16 + gid;
#pragma unroll
        for (int na = 0; na < 4; na++) {
            int c = bn + warp_n * 32 + na * 8 + tig * 2;
            float2 bb = *(const float2*)&bias[c];
            float o00 = acc[ma][na][0] + bb.x, o01 = acc[ma][na][1] + bb.y;
            float o10 = acc[ma][na][2] + bb.x, o11 = acc[ma][na][3] + bb.y;
            if (outHalf) {
                __half* Ch = (__half*)C;
                if (r < M)
                    *(uint32_t*)&Ch[(size_t)r * DIM + c] = packh2(o00, o01);
                if (r + 8 < M)
                    *(uint32_t*)&Ch[(size_t)(r + 8) * DIM + c] = packh2(o10, o11);
            } else {
                float* Cf = (float*)C;
                if (r < M)
                    *(float2*)&Cf[(size_t)r * DIM + c] = make_float2(o00, o01);
                if (r + 8 < M)
                    *(float2*)&Cf[(size_t)(r + 8) * DIM + c] = make_float2(o10, o11);
            }
        }
    }
}

// ---------------------------------------------------------------------------
// Fused RMSNorm + 3D RoPE, block-per-token, vectorized loads.
// ---------------------------------------------------------------------------
__global__ void norm_rope_h_kernel(__half* __restrict__ q, __half* __restrict__ k,
                                   const float* __restrict__ gq,
                                   const float* __restrict__ gk,
                                   const float* __restrict__ freqs,
                                   const int* __restrict__ grid_sizes) {
    const int l = blockIdx.x;
    const int tid = threadIdx.x;
    __shared__ float red[64];
    __shared__ float s_invq, s_invk;

    __half* qr = q + (size_t)l * DIM;
    __half* kr = k + (size_t)l * DIM;

    // sumsq: 192 uint4 granules (8 halves) each for q and k
    float sq = 0.f, sk = 0.f;
    if (tid < DIM / 8) {   // 192
        uint4 qv = *(const uint4*)&qr[tid * 8];
        uint4 kv = *(const uint4*)&kr[tid * 8];
        sq = sumsq8(qv);
        sk = sumsq8(kv);
    }
#pragma unroll
    for (int o = 16; o; o >>= 1) {
        sq += __shfl_xor_sync(0xffffffffu, sq, o);
        sk += __shfl_xor_sync(0xffffffffu, sk, o);
    }
    int wid = tid >> 5, lid = tid & 31;
    if (lid == 0) { red[wid] = sq; red[32 + wid] = sk; }
    __syncthreads();
    if (tid == 0) {
        float t = 0.f;
        for (int i = 0; i < (int)(blockDim.x >> 5); i++) t += red[i];
        s_invq = rsqrtf(t / DIM + EPS);
    }
    if (tid == 1) {
        float t = 0.f;
        for (int i = 0; i < (int)(blockDim.x >> 5); i++) t += red[32 + i];
        s_invk = rsqrtf(t / DIM + EPS);
    }
    __syncthreads();
    const float invq = s_invq, invk = s_invk;

    const int hh = grid_sizes[1], ww = grid_sizes[2];
    const int hw = hh * ww;
    const int fi = l / hw;
    const int rem = l - fi * hw;
    const int hi = rem / ww;
    const int wi = rem - hi * ww;

    for (int p = tid; p < NH * CPAIR; p += blockDim.x) {
        int c = p & (CPAIR - 1);
        int d0 = (p >> 6) * HD + 2 * c;
        int pos = (c < 22) ? fi : ((c < 43) ? hi : wi);
        const float* R = freqs + ((size_t)pos * CPAIR + c) * 4;
        float r00 = R[0], r01 = R[1], r10 = R[2], r11 = R[3];
        float2 gqv = *(const float2*)&gq[d0];
        float2 gkv = *(const float2*)&gk[d0];

        uint32_t qp = *(uint32_t*)&qr[d0];
        float2 qf = __half22float2(*(__half2*)&qp);
        float x0 = qf.x * invq * gqv.x;
        float x1 = qf.y * invq * gqv.y;
        *(uint32_t*)&qr[d0] = packh2(r00 * x0 + r01 * x1, r10 * x0 + r11 * x1);

        uint32_t kp = *(uint32_t*)&kr[d0];
        float2 kf = __half22float2(*(__half2*)&kp);
        x0 = kf.x * invk * gkv.x;
        x1 = kf.y * invk * gkv.y;
        *(uint32_t*)&kr[d0] = packh2(r00 * x0 + r01 * x1, r10 * x0 + r11 * x1);
    }
}

// ===========================================================================
// fp16 mma flash attention, frozen-max + f16x2 exp, single-barrier loop
// (R14 best, unchanged).
// ===========================================================================
#define AQT 64
#define AKC 64
#define AKSTRB 272
#define ABUF (2 * AKC * AKSTRB)
#define ATT_SMEM (2 * ABUF)              // 69632

__device__ __forceinline__ void attn_load(char* buf,
                                          const __half* __restrict__ K,
                                          const __half* __restrict__ V,
                                          int kc, int seqlen, int head,
                                          int tid, bool full) {
#pragma unroll
    for (int it = 0; it < 16; it++) {
        int s = tid + it * 128;
        int mat = s >> 10;
        int idx = s & 1023;
        int row = idx >> 4, quad = idx & 15;
        int gk = kc + row;
        int gkc = full ? gk : ((gk < seqlen) ? gk : 0);
        const __half* src = (mat ? V : K)
            + (size_t)gkc * DIM + head * HD + quad * 8;
        unsigned dst = smem_u32(buf) + mat * (AKC * AKSTRB)
            + row * AKSTRB + quad * 16;
        int sz = (full || gk < seqlen) ? 16 : 0;
        asm volatile("cp.async.cg.shared.global [%0], [%1], 16, %2;\n"
                     :: "r"(dst), "l"(src), "r"(sz));
    }
    asm volatile("cp.async.commit_group;\n");
}

template <int MODE>   // 0 = first (sets max), 1 = full frozen, 2 = masked frozen
__device__ __forceinline__ void attn_chunk(const char* buf, int kc, int seqlen,
                                           const uint32_t qa[8][4],
                                           float oacc[16][4],
                                           float& m0, float& m1,
                                           float& l0, float& l1,
                                           unsigned ksOff, unsigned vsOff) {
    const unsigned ksB = smem_u32(buf) + ksOff;
    const unsigned vsB = smem_u32(buf) + AKC * AKSTRB + vsOff;
    const int lane = threadIdx.x & 31;
    const int tig = lane & 3;

    // ---- S = Q @ K^T ----
    float sacc[8][4];
#pragma unroll
    for (int na = 0; na < 8; na++)
#pragma unroll
        for (int j = 0; j < 4; j++) sacc[na][j] = 0.f;
#pragma unroll
    for (int kk = 0; kk < 8; kk++) {
#pragma unroll
        for (int p = 0; p < 4; p++) {
            uint32_t b[4];
            LDSM4(b[0], b[1], b[2], b[3], ksB + p * (16 * AKSTRB) + kk * 32);
            mma16(sacc[2 * p], qa[kk], b[0], b[1]);
            mma16(sacc[2 * p + 1], qa[kk], b[2], b[3]);
        }
    }

    if (MODE == 0) {
        float mx0 = -1e30f, mx1 = -1e30f;
#pragma unroll
        for (int na = 0; na < 8; na++) {
            mx0 = fmaxf(mx0, fmaxf(sacc[na][0], sacc[na][1]));
            mx1 = fmaxf(mx1, fmaxf(sacc[na][2], sacc[na][3]));
        }
#pragma unroll
        for (int o = 1; o <= 2; o <<= 1) {
            mx0 = fmaxf(mx0, __shfl_xor_sync(0xffffffffu, mx0, o));
            mx1 = fmaxf(mx1, __shfl_xor_sync(0xffffffffu, mx1, o));
        }
        m0 = mx0 * SCALE_L2E; m1 = mx1 * SCALE_L2E;
    }

    // ---- fused exp (f16x2) + PV ----
    __half2 lacc01 = __floats2half2_rn(0.f, 0.f);
    __half2 lacc23 = __floats2half2_rn(0.f, 0.f);
#pragma unroll
    for (int j = 0; j < 4; j++) {
        uint32_t pa[4];
#pragma unroll
        for (int h = 0; h < 2; h++) {
            int na = 2 * j + h;
            float u0 = fmaf(sacc[na][0], SCALE_L2E, -m0);
            float u1 = fmaf(sacc[na][1], SCALE_L2E, -m0);
            float u2 = fmaf(sacc[na][2], SCALE_L2E, -m1);
            float u3 = fmaf(sacc[na][3], SCALE_L2E, -m1);
            if (MODE == 2) {
                int col = kc + na * 8 + 2 * tig;
                if (col >= seqlen)     { u0 = -100.f; u2 = -100.f; }
                if (col + 1 >= seqlen) { u1 = -100.f; u3 = -100.f; }
            }
            uint32_t p01 = hex2(packh2(u0, u1));
            uint32_t p23 = hex2(packh2(u2, u3));
            lacc01 = __hadd2(lacc01, *(__half2*)&p01);
            lacc23 = __hadd2(lacc23, *(__half2*)&p23);
            pa[2 * h] = p01; pa[2 * h + 1] = p23;
        }
#pragma unroll
        for (int dp = 0; dp < 8; dp++) {
            uint32_t b[4];
            LDSM4T(b[0], b[1], b[2], b[3], vsB + j * (16 * AKSTRB) + dp * 32);
            mma16(oacc[2 * dp], pa, b[0], b[1]);
            mma16(oacc[2 * dp + 1], pa, b[2], b[3]);
        }
    }
    float2 f01 = __half22float2(lacc01);
    float2 f23 = __half22float2(lacc23);
    l0 += f01.x + f01.y;
    l1 += f23.x + f23.y;
}

__global__ __launch_bounds__(128, 3)
void attn_h_kernel(const __half* __restrict__ Q, const __half* __restrict__ K,
                   const __half* __restrict__ V, __half* __restrict__ O,
                   const int* __restrict__ seq_lens, int Ltot) {
    extern __shared__ char smh[];

    const int head = blockIdx.y;
    const int q0 = blockIdx.x * AQT;
    const int tid = threadIdx.x;
    const int w = tid >> 5;
    const int lane = tid & 31;
    const int gid = lane >> 2, tig = lane & 3;
    const int seqlen = seq_lens[0];

    const unsigned ksOff =
        (unsigned)(((lane & 7) + ((lane >> 4) & 1) * 8) * AKSTRB
                   + ((lane >> 3) & 1) * 16);
    const unsigned vsOff =
        (unsigned)(((lane & 7) + ((lane >> 3) & 1) * 8) * AKSTRB
                   + ((lane >> 4) & 1) * 16);

    const int r0 = q0 + w * 16 + gid;
    const int r1 = r0 + 8;
    const __half* q0p = Q + (size_t)((r0 < Ltot) ? r0 : (Ltot - 1)) * DIM + head * HD;
    const __half* q1p = Q + (size_t)((r1 < Ltot) ? r1 : (Ltot - 1)) * DIM + head * HD;

    uint32_t qa[8][4];
#pragma unroll
    for (int kk = 0; kk < 8; kk++) {
        qa[kk][0] = *(const uint32_t*)&q0p[kk * 16 + 2 * tig];
        qa[kk][1] = *(const uint32_t*)&q1p[kk * 16 + 2 * tig];
        qa[kk][2] = *(const uint32_t*)&q0p[kk * 16 + 8 + 2 * tig];
        qa[kk][3] = *(const uint32_t*)&q1p[kk * 16 + 8 + 2 * tig];
    }

    float oacc[16][4];
#pragma unroll
    for (int i = 0; i < 16; i++)
#pragma unroll
        for (int j = 0; j < 4; j++) oacc[i][j] = 0.f;
    float m0 = 0.f, m1 = 0.f, l0 = 0.f, l1 = 0.f;

    const int nchunk = (seqlen + AKC - 1) / AKC;
    const int nfull = seqlen / AKC;

    attn_load(smh, K, V, 0, seqlen, head, tid, 0 < nfull);

    for (int ch = 0; ch < nchunk; ch++) {
        asm volatile("cp.async.wait_group 0;\n");
        __syncthreads();
        if (ch + 1 < nchunk)
            attn_load(smh + ((ch + 1) & 1) * ABUF, K, V, (ch + 1) * AKC,
                      seqlen, head, tid, (ch + 1) < nfull);
        const char* buf = smh + (ch & 1) * ABUF;
        if (ch == 0)
            attn_chunk<0>(buf, 0, seqlen, qa, oacc, m0, m1, l0, l1, ksOff, vsOff);
        else if (ch < nfull)
            attn_chunk<1>(buf, ch * AKC, seqlen, qa, oacc, m0, m1, l0, l1,
                          ksOff, vsOff);
        else
            attn_chunk<2>(buf, ch * AKC, seqlen, qa, oacc, m0, m1, l0, l1,
                          ksOff, vsOff);
    }

#pragma unroll
    for (int o = 1; o <= 2; o <<= 1) {
        l0 += __shfl_xor_sync(0xffffffffu, l0, o);
        l1 += __shfl_xor_sync(0xffffffffu, l1, o);
    }

    float inv0 = (l0 > 0.f) ? 1.0f / l0 : 0.f;
    float inv1 = (l1 > 0.f) ? 1.0f / l1 : 0.f;
#pragma unroll
    for (int na = 0; na < 16; na++) {
        int c = head * HD + na * 8 + 2 * tig;
        if (r0 < Ltot)
            *(uint32_t*)&O[(size_t)r0 * DIM + c] =
                packh2(oacc[na][0] * inv0, oacc[na][1] * inv0);
        if (r1 < Ltot)
            *(uint32_t*)&O[(size_t)r1 * DIM + c] =
                packh2(oacc[na][2] * inv1, oacc[na][3] * inv1);
    }
}

// ---------------------------------------------------------------------------
// Inputs: 0:x 1:Wq 2:bq 3:Wk 4:bk 5:Wv 6:bv 7:Wo 8:bo 9:gq 10:gk
//         11:seq_lens 12:grid_sizes 13:freqs
// ---------------------------------------------------------------------------
extern "C" void kernel_launch(void* const* d_in, const int* in_sizes, int n_in,
                              void* d_out, int out_size) {
    const float* x  = (const float*)d_in[0];
    const float* Wq = (const float*)d_in[1];
    const float* bq = (const float*)d_in[2];
    const float* Wk = (const float*)d_in[3];
    const float* bk = (const float*)d_in[4];
    const float* Wv = (const float*)d_in[5];
    const float* bv = (const float*)d_in[6];
    const float* Wo = (const float*)d_in[7];
    const float* bo = (const float*)d_in[8];
    const float* gq = (const float*)d_in[9];
    const float* gk = (const float*)d_in[10];
    const int* seq_lens   = (const int*)d_in[11];
    const int* grid_sizes = (const int*)d_in[12];
    const float* freqs    = (const float*)d_in[13];
    float* out = (float*)d_out;

    const int L = in_sizes[0] / DIM;   // 2400

    __half *pxh, *pwh, *pqh, *pkh, *pvh, *pah;
    cudaGetSymbolAddress((void**)&pxh, g_xh);
    cudaGetSymbolAddress((void**)&pwh, g_wh);
    cudaGetSymbolAddress((void**)&pqh, g_qh);
    cudaGetSymbolAddress((void**)&pkh, g_kh);
    cudaGetSymbolAddress((void**)&pvh, g_vh);
    cudaGetSymbolAddress((void**)&pah, g_ah);

    cudaFuncSetAttribute(gemm_h_kernel,
                         cudaFuncAttributeMaxDynamicSharedMemorySize, HGEMM_SMEM);
    cudaFuncSetAttribute(attn_h_kernel,
                         cudaFuncAttributeMaxDynamicSharedMemorySize, ATT_SMEM);

    // --- convert inputs to fp16 ---
    const int nW4 = DIM * DIM / 4;
    const int nX4 = L * DIM / 4;
    const int tot = nX4 + 4 * nW4;
    cvt_all_kernel<<<(tot + 255) / 256, 256>>>(x, Wq, Wk, Wv, Wo,
                                               pxh, pwh, nX4, nW4);

    const int mt = (L + 127) / 128;   // 19

    // --- fused QKV projection (fp16 out) ---
    dim3 gq3(DIM / 128, mt, 3);
    gemm_h_kernel<<<gq3, 256, HGEMM_SMEM>>>(pxh, pwh, bq, bk, bv,
                                            pqh, pkh, pvh, L, 3, 1);

    norm_rope_h_kernel<<<L, 256>>>(pqh, pkh, gq, gk, freqs, grid_sizes);

    dim3 ga((L + AQT - 1) / AQT, NH);
    attn_h_kernel<<<ga, 128, ATT_SMEM>>>(pqh, pkh, pvh, pah, seq_lens, L);

    // --- output projection (fp32 out) ---
    dim3 gg(DIM / 128, mt, 1);
    gemm_h_kernel<<<gg, 256, HGEMM_SMEM>>>(pah, pwh + 3 * (size_t)DIM * DIM,
                                           bo, bo, bo, out, out, out, L, 1, 0);
}